// round 3
// baseline (speedup 1.0000x reference)
#include <cuda_runtime.h>
#include <cstdint>

// Cost volume, B=8 C=128 H=128 W=256, d=4 -> 81 shifts.
// out[b, i*9+j, h, w] = (1/C) * sum_c f1[b,c,h,w] * f2[b,c,h+i-4,w+j-4] (zero pad)

namespace {
constexpr int Bc = 8;
constexpr int Cc = 128;
constexpr int Hc = 128;
constexpr int Wc = 256;
constexpr int Dd = 4;
constexpr int Ss = 9;          // 2d+1
constexpr int NS = 81;         // Ss*Ss
constexpr int TH = 16;         // tile rows
constexpr int TW = 32;         // tile cols
constexpr int F2H = TH + 2 * Dd;   // 24
constexpr int F2W = TW + 2 * Dd;   // 40 (float4-aligned since w0 is 32-aligned)
constexpr int HW = Hc * Wc;
constexpr int NLOAD = F2H * (F2W / 4);  // 240 float4 loads per channel tile
}

__global__ __launch_bounds__(256, 1)
void cost_volume_kernel(const float* __restrict__ f1,
                        const float* __restrict__ f2,
                        float* __restrict__ out) {
    __shared__ float sf2[3][F2H][F2W];   // 3-stage pipeline, 11.25 KB

    const int tid = threadIdx.x;
    const int tx = tid & 15;             // 16 pixel-pairs across w
    const int ty = tid >> 4;             // 16 rows
    const int w0 = blockIdx.x * TW;
    const int h0 = blockIdx.y * TH;
    const int b  = blockIdx.z;

    // ---- cp.async loader mapping: thread t<240 loads one float4 per channel ----
    const int  lrow   = tid / 10;                 // 0..23
    const int  lc4    = tid % 10;                 // 0..9
    const int  gh     = h0 - Dd + lrow;
    const int  gw     = w0 - Dd + 4 * lc4;       // multiple of 4 -> float4 aligned
    const bool loader = (tid < NLOAD);
    const bool inb    = loader && ((unsigned)gh < (unsigned)Hc) &&
                                  ((unsigned)gw < (unsigned)Wc);
    const size_t f2base = inb ? ((((size_t)b * Cc) * Hc + gh) * (size_t)Wc + gw) : 0;
    const int    srcsz  = inb ? 16 : 0;          // 0 -> zero-fill 16B (padding)

    auto issue = [&](int ch, int buf) {
        if (loader) {
            uint32_t dst = (uint32_t)__cvta_generic_to_shared(&sf2[buf][lrow][4 * lc4]);
            const float* src = f2 + f2base + (size_t)ch * HW;
            asm volatile("cp.async.cg.shared.global [%0], [%1], 16, %2;"
                         :: "r"(dst), "l"(src), "r"(srcsz));
        }
    };

    // Prologue: stage channels 0 and 1
    issue(0, 0);
    asm volatile("cp.async.commit_group;" ::: "memory");
    issue(1, 1);
    asm volatile("cp.async.commit_group;" ::: "memory");

    // Per-thread f1 pointer (2 adjacent pixels, coalesced float2)
    const float* f1p = f1 + (((size_t)b * Cc) * Hc + (h0 + ty)) * (size_t)Wc
                          + (w0 + 2 * tx);
    float2 f1v = *(const float2*)f1p;   // channel 0

    float acc0[NS], acc1[NS];
#pragma unroll
    for (int s = 0; s < NS; ++s) { acc0[s] = 0.0f; acc1[s] = 0.0f; }

#pragma unroll 1
    for (int ch = 0; ch < Cc; ++ch) {
        // Ensure channel ch's tile is resident (newest group may stay in flight)
        asm volatile("cp.async.wait_group 1;" ::: "memory");
        __syncthreads();

        // Stage channel ch+2 (buffer (ch+2)%3: distinct from read buf and in-flight buf;
        // its previous readers finished before the barrier above)
        if (ch + 2 < Cc) issue(ch + 2, (ch + 2) % 3);
        asm volatile("cp.async.commit_group;" ::: "memory");

        // Prefetch next channel's f1 pair
        float2 f1n = make_float2(0.0f, 0.0f);
        if (ch + 1 < Cc) f1n = *(const float2*)(f1p + (size_t)(ch + 1) * HW);

        const int buf = ch % 3;
        const float* rowbase = &sf2[buf][ty][2 * tx];

#pragma unroll
        for (int i = 0; i < Ss; ++i) {
            // 10-float sliding window serves 9 dx shifts x 2 pixels
            float win[10];
            const float* r = rowbase + i * F2W;
#pragma unroll
            for (int k = 0; k < 5; ++k) {
                float2 v = *(const float2*)(r + 2 * k);   // 8B-aligned LDS.64
                win[2 * k]     = v.x;
                win[2 * k + 1] = v.y;
            }
#pragma unroll
            for (int j = 0; j < Ss; ++j) {
                acc0[i * Ss + j] = fmaf(f1v.x, win[j],     acc0[i * Ss + j]);
                acc1[i * Ss + j] = fmaf(f1v.y, win[j + 1], acc1[i * Ss + j]);
            }
        }
        f1v = f1n;
    }

    // Epilogue: 81 coalesced float2 stores per thread
    const float scale = 1.0f / (float)Cc;
    float* op = out + (((size_t)b * NS) * Hc + (h0 + ty)) * (size_t)Wc + (w0 + 2 * tx);
#pragma unroll
    for (int s = 0; s < NS; ++s) {
        float2 v;
        v.x = acc0[s] * scale;
        v.y = acc1[s] * scale;
        *(float2*)(op + (size_t)s * HW) = v;
    }
}

extern "C" void kernel_launch(void* const* d_in, const int* in_sizes, int n_in,
                              void* d_out, int out_size) {
    const float* f1 = (const float*)d_in[0];
    const float* f2 = (const float*)d_in[1];
    float* out = (float*)d_out;
    // d_in[2] is d=4 (fixed by problem shapes; hardcoded)
    dim3 grid(Wc / TW, Hc / TH, Bc);   // 8 x 8 x 8 = 512 blocks
    cost_volume_kernel<<<grid, 256>>>(f1, f2, out);
}